// round 10
// baseline (speedup 1.0000x reference)
#include <cuda_runtime.h>
#include <cstdint>

// Problem constants: SUPPORT=(16,16), N_NODES=100000, F=64, B=4096
#define BATCH_N    4096
#define SUP        16
#define FDIM       64
#define ROW_LEN    65          // 1 weight col + 64 features
#define ROWS_PER_B 1088        // 2 * 16 * 34
#define GROUP_ROWS 34          // 2 + 2*16
#define N_GROUPS   (BATCH_N * 2 * SUP)   // 131072 warps/groups
#define WARPS_PER_BLOCK 8
#define THREADS (WARPS_PER_BLOCK * 32)
#define HALF_ROWS   17
#define HALF_FLOATS (HALF_ROWS * ROW_LEN)   // 1105
#define BUF_FLOATS  1108                    // 1105 + up to 3 pad for 16B phase
#define FULLMASK 0xffffffffu

__global__ __launch_bounds__(THREADS, 6)
void gae_gather_wstage_kernel(const int*   __restrict__ node_ids,
                              const float* __restrict__ features,
                              const int*   __restrict__ in_sample,
                              const int*   __restrict__ out_sample,
                              const float* __restrict__ in_amnt,
                              const float* __restrict__ out_amnt,
                              float*       __restrict__ feat_out,
                              float*       __restrict__ w_out) {
    __shared__ alignas(16) float sbuf[WARPS_PER_BLOCK][BUF_FLOATS];   // 35,456 B

    const int warp = threadIdx.x >> 5;
    const int lane = threadIdx.x & 31;
    const int g = blockIdx.x * WARPS_PER_BLOCK + warp;

    const int b    = g >> 5;        // 32 groups per batch element
    const int rem  = g & 31;
    const int half = rem >> 4;      // 0 = in-branch at hop1, 1 = out-branch
    const int i    = rem & 15;      // first-hop neighbor index

    const int n = node_ids[b];
    const int*   s1 = half ? out_sample : in_sample;
    const float* a1 = half ? out_amnt  : in_amnt;
    const int   n1 = s1[n * SUP + i];
    const float w1 = a1[n * SUP + i];

    // Per-lane (node, scalar) for row r = lane (0..31).
    int   mA;  float sA;
    {
        const int r = lane;
        if (r == 0 || r == 17) { mA = n1; sA = w1; }
        else if (r <= 16)      { mA = in_sample [n1 * SUP + (r - 1)];
                                 sA = in_amnt   [n1 * SUP + (r - 1)]; }
        else                   { mA = out_sample[n1 * SUP + (r - 18)];
                                 sA = out_amnt  [n1 * SUP + (r - 18)]; }
    }
    // Rows 32,33 on lanes 0,1.
    int mB = 0; float sB = 0.f;
    if (lane < 2) {
        mB = out_sample[n1 * SUP + (14 + lane)];
        sB = out_amnt  [n1 * SUP + (14 + lane)];
    }

    const uint32_t rowbase = (uint32_t)b * ROWS_PER_B + half * 544 + i * GROUP_ROWS;

    // Weights: w1^2 for self-rows, w2*w1 otherwise (streaming stores).
    {
        const float wv = (lane == 0 || lane == 17) ? (w1 * w1) : (sA * w1);
        __stcs(&w_out[rowbase + lane], wv);
        if (lane < 2) __stcs(&w_out[rowbase + 32 + lane], sB * w1);
    }

    const uint32_t G = rowbase * (uint32_t)ROW_LEN;   // group start, flat float idx (<2^31)
    float* buf = sbuf[warp];

    #pragma unroll
    for (int h = 0; h < 2; h++) {
        const uint32_t start = G + (uint32_t)h * HALF_FLOATS;
        const int pad = (int)(start & 3);             // 16B phase of this half

        // ---- Fill: 17 rows into smem at output layout (+pad) ----
        float* rowp = buf + pad;
        #pragma unroll 4
        for (int rl = 0; rl < HALF_ROWS; rl++, rowp += ROW_LEN) {
            const int rr = h * HALF_ROWS + rl;        // 0..33
            int m; float s;
            if (rr < 32) {
                m = __shfl_sync(FULLMASK, mA, rr);
                s = __shfl_sync(FULLMASK, sA, rr);
            } else {
                m = __shfl_sync(FULLMASK, mB, rr - 32);
                s = __shfl_sync(FULLMASK, sB, rr - 32);
            }
            const float* src = features + (size_t)m * FDIM;
            const float v0 = __ldg(src + lane);       // feats 0..31  (1 wavefront)
            const float v1 = __ldg(src + lane + 32);  // feats 32..63 (1 wavefront)
            if (lane == 0) rowp[0] = s;
            rowp[1 + lane]  = v0;                     // stride-1 STS, conflict-free
            rowp[33 + lane] = v1;
        }
        __syncwarp();

        // ---- Drain: ragged head, aligned float4 body, ragged tail ----
        const int head = (4 - pad) & 3;
        const int nf4  = (HALF_FLOATS - head) >> 2;   // 275 or 276
        const int tail = HALF_FLOATS - head - (nf4 << 2);
        float* gbase = feat_out + start;

        if (lane < head) __stcs(&gbase[lane], buf[pad + lane]);

        const float4* s4 = (const float4*)(buf + pad + head);   // 16B-aligned
        float4*       g4 = (float4*)(gbase + head);             // 16B-aligned
        for (int t = lane; t < nf4; t += 32)
            __stcs(&g4[t], s4[t]);                    // LDS.128 -> STG.128.cs

        const int toff = head + (nf4 << 2);
        if (lane < tail) __stcs(&gbase[toff + lane], buf[pad + toff + lane]);
        __syncwarp();                                 // buffer reuse barrier
    }
}

extern "C" void kernel_launch(void* const* d_in, const int* in_sizes, int n_in,
                              void* d_out, int out_size) {
    const int*   node_ids = (const int*)  d_in[0];
    const float* features = (const float*)d_in[1];
    const int*   in_samp  = (const int*)  d_in[2];
    const int*   out_samp = (const int*)  d_in[3];
    const float* in_amnt  = (const float*)d_in[4];
    const float* out_amnt = (const float*)d_in[5];

    float* feat_out = (float*)d_out;
    float* w_out    = feat_out + (size_t)BATCH_N * ROWS_PER_B * ROW_LEN;

    const int blocks = N_GROUPS / WARPS_PER_BLOCK;   // 16384
    gae_gather_wstage_kernel<<<blocks, THREADS>>>(node_ids, features, in_samp, out_samp,
                                                  in_amnt, out_amnt, feat_out, w_out);
}

// round 15
// speedup vs baseline: 1.6311x; 1.6311x over previous
#include <cuda_runtime.h>
#include <cstdint>

// Problem constants: SUPPORT=(16,16), N_NODES=100000, F=64, B=4096
#define BATCH_N    4096
#define SUP        16
#define FDIM       64
#define ROW_LEN    65          // 1 weight col + 64 features
#define ROWS_PER_B 1088        // 2 * 16 * 34
#define GROUP_ROWS 34          // 2 + 2*16
#define N_GROUPS   (BATCH_N * 2 * SUP)   // 131072 warps/groups
#define WARPS_PER_BLOCK 8
#define THREADS (WARPS_PER_BLOCK * 32)
#define FULLMASK 0xffffffffu

__global__ __launch_bounds__(THREADS)
void gae_gather_seg_kernel(const int*   __restrict__ node_ids,
                           const float* __restrict__ features,
                           const int*   __restrict__ in_sample,
                           const int*   __restrict__ out_sample,
                           const float* __restrict__ in_amnt,
                           const float* __restrict__ out_amnt,
                           float*       __restrict__ feat_out,
                           float*       __restrict__ w_out) {
    const int warp = threadIdx.x >> 5;
    const int lane = threadIdx.x & 31;
    const int g = blockIdx.x * WARPS_PER_BLOCK + warp;

    const int b    = g >> 5;        // 32 groups per batch element
    const int rem  = g & 31;
    const int half = rem >> 4;      // 0 = in-branch at hop1, 1 = out-branch
    const int i    = rem & 15;      // first-hop neighbor index

    const int n = node_ids[b];
    const int*   s1 = half ? out_sample : in_sample;
    const float* a1 = half ? out_amnt  : in_amnt;
    const int   n1 = s1[n * SUP + i];
    const float w1 = a1[n * SUP + i];

    // Per-lane (node, scalar) for row r = lane (0..31).
    int   mA;  float sA;
    {
        const int r = lane;
        if (r == 0 || r == 17) { mA = n1; sA = w1; }
        else if (r <= 16)      { mA = in_sample [n1 * SUP + (r - 1)];
                                 sA = in_amnt   [n1 * SUP + (r - 1)]; }
        else                   { mA = out_sample[n1 * SUP + (r - 18)];
                                 sA = out_amnt  [n1 * SUP + (r - 18)]; }
    }
    // Rows 32,33 on lanes 0,1.
    int mB = 0; float sB = 0.f;
    if (lane < 2) {
        mB = out_sample[n1 * SUP + (14 + lane)];
        sB = out_amnt  [n1 * SUP + (14 + lane)];
    }

    const uint32_t rowbase = (uint32_t)b * ROWS_PER_B + half * 544 + i * GROUP_ROWS;

    // Weights: w1^2 for self-rows, w2*w1 otherwise.
    {
        const float wv = (lane == 0 || lane == 17) ? (w1 * w1) : (sA * w1);
        __stcs(&w_out[rowbase + lane], wv);
        if (lane < 2) __stcs(&w_out[rowbase + 32 + lane], sB * w1);
    }

    // ---- Feature rows: rotated loads + merged full-line stores,
    //      loop segmented around the single algebraic wrap point ----
    const uint32_t G = rowbase * (uint32_t)ROW_LEN;  // group start (< 2^31)
    const int a0 = 2 * i;                            // == G & 31 (proved: rowbase mod 32 = 2i)
    int k = (lane - a0 - 1) & 31;                    // rotated lane for loads
    float* myp = feat_out + (G - (uint32_t)a0) + (uint32_t)lane;

    // Row 0 prologue: predicated head + full chunk1.
    int   m = __shfl_sync(FULLMASK, mA, 0);
    float s = __shfl_sync(FULLMASK, sA, 0);
    const float* src = features + ((uint32_t)m << 6);
    float v0 = __ldg(src + k);
    float v1 = __ldg(src + k + 32);
    if (lane >= a0) __stcs(&myp[0], (lane == a0) ? s : v0);
    __stcs(&myp[32], (lane <= a0) ? v0 : v1);

    int a = a0;
    // Segment 1: rr = 1 .. 31-a0  (a = a0+rr <= 31; always mA; no wrap)
    #pragma unroll 4
    for (int rr = 1; rr <= 31 - a0; rr++) {
        const float pv1 = v1;
        a++; k = (k - 1) & 31;
        m = __shfl_sync(FULLMASK, mA, rr);
        s = __shfl_sync(FULLMASK, sA, rr);
        src = features + ((uint32_t)m << 6);
        v0 = __ldg(src + k);
        v1 = __ldg(src + k + 32);
        __stcs(&myp[64], (lane < a) ? pv1 : ((lane == a) ? s : v0));  // merged, full line
        __stcs(&myp[96], (lane <= a) ? v0 : v1);                      // chunk1, full line
        myp += 64;
    }

    // Wrap iteration: rr = 32-a0  (pa=31 -> a=0). Three full lines.
    {
        const int rr = 32 - a0;
        const float pv1 = v1;
        k = (k - 1) & 31;                            // == (lane-1)&31
        const int   msrc = (rr < 32) ? mA : mB;      // rr==32 only when i==0
        const float ssrc = (rr < 32) ? sA : sB;
        m = __shfl_sync(FULLMASK, msrc, rr & 31);
        s = __shfl_sync(FULLMASK, ssrc, rr & 31);
        src = features + ((uint32_t)m << 6);
        v0 = __ldg(src + k);
        v1 = __ldg(src + k + 32);
        __stcs(&myp[64],  pv1);                      // full prev-row tail
        __stcs(&myp[96],  (lane == 0) ? s : v0);     // full cur-row head (a=0)
        __stcs(&myp[128], (lane == 0) ? v0 : v1);    // chunk1
        myp += 96;
        a = 0;
    }

    // Segment 2: rr = 33-a0 .. 33  (a = 1..a0+1; no wrap; mA/mB select)
    #pragma unroll 4
    for (int rr = 33 - a0; rr <= 33; rr++) {
        const float pv1 = v1;
        a++; k = (k - 1) & 31;
        const int   msrc = (rr < 32) ? mA : mB;
        const float ssrc = (rr < 32) ? sA : sB;
        m = __shfl_sync(FULLMASK, msrc, rr & 31);
        s = __shfl_sync(FULLMASK, ssrc, rr & 31);
        src = features + ((uint32_t)m << 6);
        v0 = __ldg(src + k);
        v1 = __ldg(src + k + 32);
        __stcs(&myp[64], (lane < a) ? pv1 : ((lane == a) ? s : v0));
        __stcs(&myp[96], (lane <= a) ? v0 : v1);
        myp += 64;
    }

    // Tail: a == a0+1 == 2i+1. Lanes above belong to the next group.
    if (lane <= a) __stcs(&myp[64], v1);
}

extern "C" void kernel_launch(void* const* d_in, const int* in_sizes, int n_in,
                              void* d_out, int out_size) {
    const int*   node_ids = (const int*)  d_in[0];
    const float* features = (const float*)d_in[1];
    const int*   in_samp  = (const int*)  d_in[2];
    const int*   out_samp = (const int*)  d_in[3];
    const float* in_amnt  = (const float*)d_in[4];
    const float* out_amnt = (const float*)d_in[5];

    float* feat_out = (float*)d_out;
    float* w_out    = feat_out + (size_t)BATCH_N * ROWS_PER_B * ROW_LEN;

    const int blocks = N_GROUPS / WARPS_PER_BLOCK;   // 16384
    gae_gather_seg_kernel<<<blocks, THREADS>>>(node_ids, features, in_samp, out_samp,
                                               in_amnt, out_amnt, feat_out, w_out);
}